// round 6
// baseline (speedup 1.0000x reference)
#include <cuda_runtime.h>
#include <cstdint>

// Problem constants (fixed by reference setup_inputs)
#define NB    8        // batch
#define NS    4096     // source points
#define NT    16384    // target points
#define NC    8        // channels
#define NH    10       // neighbors
#define WPB   8        // warps per block
#define FULLM 0xFFFFFFFFu

typedef unsigned long long ull;

#define BUFCAP 288     // per-warp candidate buffer (worst case 22 + 256)
#define TRIG   23      // drain when count >= TRIG

// Bitonic sort of 32 u64 keys across a warp (ascending; lane k ends with k-th smallest).
__device__ __forceinline__ ull bitonic32(ull key, int lane) {
#pragma unroll
    for (int k = 2; k <= 32; k <<= 1) {
#pragma unroll
        for (int j = k >> 1; j > 0; j >>= 1) {
            ull other = __shfl_xor_sync(FULLM, key, j);
            bool up    = ((lane & k) == 0);
            bool lower = ((lane & j) == 0);
            ull mn = (key < other) ? key : other;
            ull mx = (key < other) ? other : key;
            key = (lower == up) ? mn : mx;
        }
    }
    return key;
}

// Merge buffered candidates into the distributed top-10 (lanes 0..9), refresh thr.
__device__ __noinline__ void drain(ull& top, ull* __restrict__ buf,
                                   int& count, int lane, float& thr) {
    __syncwarp(FULLM);           // order STS pushes before LDS reads
    int cur = 0;
    while (cur < count) {
        int take = count - cur;
        if (take > 22) take = 22;
        ull v;
        if (lane < NH) {
            v = top;
        } else {
            int b = lane - NH;
            v = (b < take) ? buf[cur + b] : ~0ULL;
        }
        v = bitonic32(v, lane);
        if (lane < NH) top = v;
        cur += take;
    }
    count = 0;
    thr = __uint_as_float((unsigned)(__shfl_sync(FULLM, top, NH - 1) >> 32));
    __syncwarp(FULLM);           // buf reads done before next batch overwrites
}

#define MKKEY(dv, sidx) ((((ull)__float_as_uint(dv)) << 32) | (unsigned)(sidx))

// Distances for one 4-float4 batch held in registers p0..p3.
#define DIST8(P0, P1, P2, P3)                                                 \
    float d0 = P0.x * P0.x + P0.y * P0.y;                                     \
    float d1 = P0.z * P0.z + P0.w * P0.w;                                     \
    float d2 = P1.x * P1.x + P1.y * P1.y;                                     \
    float d3 = P1.z * P1.z + P1.w * P1.w;                                     \
    float d4 = P2.x * P2.x + P2.y * P2.y;                                     \
    float d5 = P2.z * P2.z + P2.w * P2.w;                                     \
    float d6 = P3.x * P3.x + P3.y * P3.y;                                     \
    float d7 = P3.z * P3.z + P3.w * P3.w;

#define LOAD4(P0, P1, P2, P3, J)                                              \
    P0 = __ldg(&relrow[(J)]);                                                 \
    P1 = __ldg(&relrow[(J) + 32]);                                            \
    P2 = __ldg(&relrow[(J) + 64]);                                            \
    P3 = __ldg(&relrow[(J) + 96]);

// Selection for one batch: warp-coherent prefilter, prefix-scan push, drain.
#define PROCESS(JB)                                                           \
    {                                                                         \
        float mn = fminf(fminf(fminf(d0, d1), fminf(d2, d3)),                 \
                         fminf(fminf(d4, d5), fminf(d6, d7)));                \
        if (__any_sync(FULLM, mn <= thr)) {                                   \
            int c0 = d0 <= thr, c1 = d1 <= thr, c2 = d2 <= thr, c3 = d3 <= thr; \
            int c4 = d4 <= thr, c5 = d5 <= thr, c6 = d6 <= thr, c7 = d7 <= thr; \
            int cnt = c0 + c1 + c2 + c3 + c4 + c5 + c6 + c7;                  \
            int scan = cnt;                                                   \
            _Pragma("unroll")                                                 \
            for (int s = 1; s < 32; s <<= 1) {                                \
                int y = __shfl_up_sync(FULLM, scan, s);                       \
                if (lane >= s) scan += y;                                     \
            }                                                                 \
            int total = __shfl_sync(FULLM, scan, 31);                         \
            if (total) {                                                      \
                int off = count + scan - cnt;                                 \
                if (c0) buf[off++] = MKKEY(d0, 2 * (JB));                     \
                if (c1) buf[off++] = MKKEY(d1, 2 * (JB) + 1);                 \
                if (c2) buf[off++] = MKKEY(d2, 2 * ((JB) + 32));              \
                if (c3) buf[off++] = MKKEY(d3, 2 * ((JB) + 32) + 1);          \
                if (c4) buf[off++] = MKKEY(d4, 2 * ((JB) + 64));              \
                if (c5) buf[off++] = MKKEY(d5, 2 * ((JB) + 64) + 1);          \
                if (c6) buf[off++] = MKKEY(d6, 2 * ((JB) + 96));              \
                if (c7) buf[off++] = MKKEY(d7, 2 * ((JB) + 96) + 1);          \
                count += total;                                               \
                if (count >= TRIG) drain(top, buf, count, lane, thr);         \
            }                                                                 \
        }                                                                     \
    }

__global__ __launch_bounds__(32 * WPB, 4)
void knn_idw_kernel(const float* __restrict__ x,    // [NB, NS, NC]
                    const float* __restrict__ rel,  // [NT, NS, 2]
                    float* __restrict__ out)        // [NB, NT, NC]
{
    __shared__ ull sbuf[WPB][BUFCAP];

    const int warp = threadIdx.x >> 5;
    const int lane = threadIdx.x & 31;
    const int t    = blockIdx.x * WPB + warp;     // target index (grid covers NT)
    ull* buf = sbuf[warp];

    const float4* relrow = reinterpret_cast<const float4*>(rel + (size_t)t * NS * 2);

    // Distributed warp top-10: lane k (k<10) holds k-th smallest key.
    // key = (float_bits(d2) << 32) | source_index  -> exact order, ties by lowest idx.
    ull   top   = ~0ULL;
    float thr;
    int   count = 0;

    // ---- Double-buffered pipeline: prefetch distance 2 (8 LDG.128 in flight) ----
    float4 a0, a1, a2, a3, b0, b1, b2, b3;
    LOAD4(a0, a1, a2, a3, lane);          // batch 0
    LOAD4(b0, b1, b2, b3, lane + 128);    // batch 1

    // ---- Batch 0 (peeled): seed thr, then push its survivors ----
    {
        const int jb = lane;
        DIST8(a0, a1, a2, a3);
        LOAD4(a0, a1, a2, a3, lane + 256);            // batch 2
        float mn = fminf(fminf(fminf(d0, d1), fminf(d2, d3)),
                         fminf(fminf(d4, d5), fminf(d6, d7)));
        // Seed thr: 10th-smallest of the 32 lane-mins (conservative, exact-safe).
        ull sorted = bitonic32(MKKEY(mn, lane), lane);
        thr = __uint_as_float((unsigned)(__shfl_sync(FULLM, sorted, NH - 1) >> 32));
        PROCESS(jb);
    }

    // ---- Steady state: batches 1..14, two per iteration ----
#pragma unroll 1
    for (int b = 1; b < 15; b += 2) {
        {   // odd batch b (in B regs)
            const int jb = b * 128 + lane;
            DIST8(b0, b1, b2, b3);
            LOAD4(b0, b1, b2, b3, jb + 256);          // batch b+2 (<=15 always)
            PROCESS(jb);
        }
        {   // even batch b+1 (in A regs)
            const int jb = (b + 1) * 128 + lane;
            DIST8(a0, a1, a2, a3);
            if (b + 3 < 16) { LOAD4(a0, a1, a2, a3, jb + 256); }  // batch b+3
            PROCESS(jb);
        }
    }

    // ---- Batch 15 (peeled, in B regs) ----
    {
        const int jb = 15 * 128 + lane;
        DIST8(b0, b1, b2, b3);
        PROCESS(jb);
    }

    if (count > 0) drain(top, buf, count, lane, thr);

    // ---- Weights ----
    float wk[NH];
    int   ik[NH];
    float wsum = 0.0f;
#pragma unroll
    for (int k = 0; k < NH; ++k) {
        ull kk = __shfl_sync(FULLM, top, k);
        float dd = __uint_as_float((unsigned)(kk >> 32));
        ik[k] = (int)(kk & 0xFFFFFFFFu);
        float w = 1.0f / (sqrtf(dd) + 1e-10f);
        wk[k] = w;
        wsum += w;
    }
    const float inv = 1.0f / wsum;

    // ---- Gather + weighted sum: 64 outputs (8 batch x 8 chan), 2 per lane ----
    const int bb = lane >> 3;      // 0..3
    const int c  = lane & 7;       // 0..7
    float acc0 = 0.0f, acc1 = 0.0f;
#pragma unroll
    for (int k = 0; k < NH; ++k) {
        float w = wk[k] * inv;
        const float* xs = x + (size_t)ik[k] * NC + c;
        acc0 += w * __ldg(xs + (size_t)(bb)     * NS * NC);
        acc1 += w * __ldg(xs + (size_t)(bb + 4) * NS * NC);
    }
    out[((size_t)(bb)     * NT + t) * NC + c] = acc0;
    out[((size_t)(bb + 4) * NT + t) * NC + c] = acc1;
}

extern "C" void kernel_launch(void* const* d_in, const int* in_sizes, int n_in,
                              void* d_out, int out_size)
{
    const float* x   = (const float*)d_in[0];   // [8, 4096, 8]
    const float* rel = (const float*)d_in[1];   // [16384, 4096, 2]
    float* out       = (float*)d_out;           // [8, 16384, 8]
    (void)in_sizes; (void)n_in; (void)out_size;

    dim3 grid(NT / WPB);      // 2048 blocks
    dim3 block(32 * WPB);     // 256 threads
    knn_idw_kernel<<<grid, block>>>(x, rel, out);
}

// round 7
// speedup vs baseline: 1.0094x; 1.0094x over previous
#include <cuda_runtime.h>
#include <cstdint>

// Problem constants (fixed by reference setup_inputs)
#define NB    8        // batch
#define NS    4096     // source points
#define NT    16384    // target points
#define NC    8        // channels
#define NH    10       // neighbors
#define WPB   8        // warps per block
#define FULLM 0xFFFFFFFFu

typedef unsigned long long ull;

#define BUFCAP 288     // per-warp candidate buffer (worst case 22 + 256)
#define TRIG   23      // drain when count >= TRIG

// Bitonic sort of 32 u64 keys across a warp (ascending; lane k ends with k-th smallest).
__device__ __forceinline__ ull bitonic32(ull key, int lane) {
#pragma unroll
    for (int k = 2; k <= 32; k <<= 1) {
#pragma unroll
        for (int j = k >> 1; j > 0; j >>= 1) {
            ull other = __shfl_xor_sync(FULLM, key, j);
            bool up    = ((lane & k) == 0);
            bool lower = ((lane & j) == 0);
            ull mn = (key < other) ? key : other;
            ull mx = (key < other) ? other : key;
            key = (lower == up) ? mn : mx;
        }
    }
    return key;
}

// Merge buffered candidates into the distributed top-10 (lanes 0..9), refresh thr.
__device__ __noinline__ void drain(ull& top, ull* __restrict__ buf,
                                   int& count, int lane, float& thr) {
    __syncwarp(FULLM);           // order STS pushes before LDS reads
    int cur = 0;
    while (cur < count) {
        int take = count - cur;
        if (take > 22) take = 22;
        ull v;
        if (lane < NH) {
            v = top;
        } else {
            int b = lane - NH;
            v = (b < take) ? buf[cur + b] : ~0ULL;
        }
        v = bitonic32(v, lane);
        if (lane < NH) top = v;
        cur += take;
    }
    count = 0;
    thr = __uint_as_float((unsigned)(__shfl_sync(FULLM, top, NH - 1) >> 32));
    __syncwarp(FULLM);           // buf reads done before next batch overwrites
}

#define MKKEY(dv, sidx) ((((ull)__float_as_uint(dv)) << 32) | (unsigned)(sidx))

// Distances for one 4-float4 batch.
#define DIST8(P0, P1, P2, P3)                                                 \
    float d0 = P0.x * P0.x + P0.y * P0.y;                                     \
    float d1 = P0.z * P0.z + P0.w * P0.w;                                     \
    float d2 = P1.x * P1.x + P1.y * P1.y;                                     \
    float d3 = P1.z * P1.z + P1.w * P1.w;                                     \
    float d4 = P2.x * P2.x + P2.y * P2.y;                                     \
    float d5 = P2.z * P2.z + P2.w * P2.w;                                     \
    float d6 = P3.x * P3.x + P3.y * P3.y;                                     \
    float d7 = P3.z * P3.z + P3.w * P3.w;

#define LOAD4(P0, P1, P2, P3, J)                                              \
    P0 = __ldg(&relrow[(J)]);                                                 \
    P1 = __ldg(&relrow[(J) + 32]);                                            \
    P2 = __ldg(&relrow[(J) + 64]);                                            \
    P3 = __ldg(&relrow[(J) + 96]);

// Selection for one batch: warp-coherent prefilter, prefix-scan push, drain.
#define PROCESS(JB)                                                           \
    {                                                                         \
        float mn = fminf(fminf(fminf(d0, d1), fminf(d2, d3)),                 \
                         fminf(fminf(d4, d5), fminf(d6, d7)));                \
        if (__any_sync(FULLM, mn <= thr)) {                                   \
            int c0 = d0 <= thr, c1 = d1 <= thr, c2 = d2 <= thr, c3 = d3 <= thr; \
            int c4 = d4 <= thr, c5 = d5 <= thr, c6 = d6 <= thr, c7 = d7 <= thr; \
            int cnt = c0 + c1 + c2 + c3 + c4 + c5 + c6 + c7;                  \
            int scan = cnt;                                                   \
            _Pragma("unroll")                                                 \
            for (int s = 1; s < 32; s <<= 1) {                                \
                int y = __shfl_up_sync(FULLM, scan, s);                       \
                if (lane >= s) scan += y;                                     \
            }                                                                 \
            int total = __shfl_sync(FULLM, scan, 31);                         \
            if (total) {                                                      \
                int off = count + scan - cnt;                                 \
                if (c0) buf[off++] = MKKEY(d0, 2 * (JB));                     \
                if (c1) buf[off++] = MKKEY(d1, 2 * (JB) + 1);                 \
                if (c2) buf[off++] = MKKEY(d2, 2 * ((JB) + 32));              \
                if (c3) buf[off++] = MKKEY(d3, 2 * ((JB) + 32) + 1);          \
                if (c4) buf[off++] = MKKEY(d4, 2 * ((JB) + 64));              \
                if (c5) buf[off++] = MKKEY(d5, 2 * ((JB) + 64) + 1);          \
                if (c6) buf[off++] = MKKEY(d6, 2 * ((JB) + 96));              \
                if (c7) buf[off++] = MKKEY(d7, 2 * ((JB) + 96) + 1);          \
                count += total;                                               \
                if (count >= TRIG) drain(top, buf, count, lane, thr);         \
            }                                                                 \
        }                                                                     \
    }

__global__ __launch_bounds__(32 * WPB, 6)
void knn_idw_kernel(const float* __restrict__ x,    // [NB, NS, NC]
                    const float* __restrict__ rel,  // [NT, NS, 2]
                    float* __restrict__ out)        // [NB, NT, NC]
{
    __shared__ ull sbuf[WPB][BUFCAP];

    const int warp = threadIdx.x >> 5;
    const int lane = threadIdx.x & 31;
    const int t    = blockIdx.x * WPB + warp;     // target index (grid covers NT)
    ull* buf = sbuf[warp];

    const float4* relrow = reinterpret_cast<const float4*>(rel + (size_t)t * NS * 2);

    // Distributed warp top-10: lane k (k<10) holds k-th smallest key.
    // key = (float_bits(d2) << 32) | source_index  -> exact order, ties by lowest idx.
    ull   top   = ~0ULL;
    float thr;
    int   count = 0;

    // ---- Prefetch distance 1 (4 LDG.128 in flight per warp; MLP comes from occupancy) ----
    float4 v0, v1, v2, v3;
    LOAD4(v0, v1, v2, v3, lane);                  // batch 0

    // ---- Batch 0 (peeled): seed thr, then push its survivors ----
    {
        const int jb = lane;
        DIST8(v0, v1, v2, v3);
        LOAD4(v0, v1, v2, v3, lane + 128);        // batch 1
        float mn = fminf(fminf(fminf(d0, d1), fminf(d2, d3)),
                         fminf(fminf(d4, d5), fminf(d6, d7)));
        // Seed thr: 10th-smallest of the 32 lane-mins (conservative & exact-safe).
        ull sorted = bitonic32(MKKEY(mn, lane), lane);
        thr = __uint_as_float((unsigned)(__shfl_sync(FULLM, sorted, NH - 1) >> 32));
        PROCESS(jb);
    }

    // ---- Steady state: batches 1..15 ----
#pragma unroll 1
    for (int b = 1; b < 16; ++b) {
        const int jb = b * 128 + lane;
        DIST8(v0, v1, v2, v3);
        if (b < 15) { LOAD4(v0, v1, v2, v3, jb + 128); }   // prefetch next batch
        PROCESS(jb);
    }

    if (count > 0) drain(top, buf, count, lane, thr);

    // ---- Weights ----
    float wk[NH];
    int   ik[NH];
    float wsum = 0.0f;
#pragma unroll
    for (int k = 0; k < NH; ++k) {
        ull kk = __shfl_sync(FULLM, top, k);
        float dd = __uint_as_float((unsigned)(kk >> 32));
        ik[k] = (int)(kk & 0xFFFFFFFFu);
        float w = 1.0f / (sqrtf(dd) + 1e-10f);
        wk[k] = w;
        wsum += w;
    }
    const float inv = 1.0f / wsum;

    // ---- Gather + weighted sum: 64 outputs (8 batch x 8 chan), 2 per lane ----
    const int bb = lane >> 3;      // 0..3
    const int c  = lane & 7;       // 0..7
    float acc0 = 0.0f, acc1 = 0.0f;
#pragma unroll
    for (int k = 0; k < NH; ++k) {
        float w = wk[k] * inv;
        const float* xs = x + (size_t)ik[k] * NC + c;
        acc0 += w * __ldg(xs + (size_t)(bb)     * NS * NC);
        acc1 += w * __ldg(xs + (size_t)(bb + 4) * NS * NC);
    }
    out[((size_t)(bb)     * NT + t) * NC + c] = acc0;
    out[((size_t)(bb + 4) * NT + t) * NC + c] = acc1;
}

extern "C" void kernel_launch(void* const* d_in, const int* in_sizes, int n_in,
                              void* d_out, int out_size)
{
    const float* x   = (const float*)d_in[0];   // [8, 4096, 8]
    const float* rel = (const float*)d_in[1];   // [16384, 4096, 2]
    float* out       = (float*)d_out;           // [8, 16384, 8]
    (void)in_sizes; (void)n_in; (void)out_size;

    dim3 grid(NT / WPB);      // 2048 blocks
    dim3 block(32 * WPB);     // 256 threads
    knn_idw_kernel<<<grid, block>>>(x, rel, out);
}

// round 8
// speedup vs baseline: 1.2468x; 1.2352x over previous
#include <cuda_runtime.h>
#include <cstdint>

// Problem constants (fixed by reference setup_inputs)
#define NB    8        // batch
#define NS    4096     // source points
#define NT    16384    // target points
#define NC    8        // channels
#define NH    10       // neighbors
#define WPB   8        // warps per block
#define FULLM 0xFFFFFFFFu

typedef unsigned long long ull;

#define BUFCAP 288     // per-warp candidate buffer (worst case 22 + 256)
#define TRIG   23      // drain when count >= TRIG

// Bitonic sort of 32 u64 keys across a warp (ascending; lane k ends with k-th smallest).
__device__ __forceinline__ ull bitonic32(ull key, int lane) {
#pragma unroll
    for (int k = 2; k <= 32; k <<= 1) {
#pragma unroll
        for (int j = k >> 1; j > 0; j >>= 1) {
            ull other = __shfl_xor_sync(FULLM, key, j);
            bool up    = ((lane & k) == 0);
            bool lower = ((lane & j) == 0);
            ull mn = (key < other) ? key : other;
            ull mx = (key < other) ? other : key;
            key = (lower == up) ? mn : mx;
        }
    }
    return key;
}

// Merge buffered candidates into the distributed top-10 (lanes 0..9), refresh thr.
__device__ __noinline__ void drain(ull& top, ull* __restrict__ buf,
                                   int& count, int lane, float& thr) {
    __syncwarp(FULLM);           // order STS pushes before LDS reads
    int cur = 0;
    while (cur < count) {
        int take = count - cur;
        if (take > 22) take = 22;
        ull v;
        if (lane < NH) {
            v = top;
        } else {
            int b = lane - NH;
            v = (b < take) ? buf[cur + b] : ~0ULL;
        }
        v = bitonic32(v, lane);
        if (lane < NH) top = v;
        cur += take;
    }
    count = 0;
    thr = __uint_as_float((unsigned)(__shfl_sync(FULLM, top, NH - 1) >> 32));
    __syncwarp(FULLM);           // buf reads done before next batch overwrites
}

#define MKKEY(dv, sidx) ((((ull)__float_as_uint(dv)) << 32) | (unsigned)(sidx))

// Distances for one 4-float4 batch.
#define DIST8(P0, P1, P2, P3)                                                 \
    float d0 = P0.x * P0.x + P0.y * P0.y;                                     \
    float d1 = P0.z * P0.z + P0.w * P0.w;                                     \
    float d2 = P1.x * P1.x + P1.y * P1.y;                                     \
    float d3 = P1.z * P1.z + P1.w * P1.w;                                     \
    float d4 = P2.x * P2.x + P2.y * P2.y;                                     \
    float d5 = P2.z * P2.z + P2.w * P2.w;                                     \
    float d6 = P3.x * P3.x + P3.y * P3.y;                                     \
    float d7 = P3.z * P3.z + P3.w * P3.w;

#define LOAD4(P0, P1, P2, P3, J)                                              \
    P0 = __ldg(&relrow[(J)]);                                                 \
    P1 = __ldg(&relrow[(J) + 32]);                                            \
    P2 = __ldg(&relrow[(J) + 64]);                                            \
    P3 = __ldg(&relrow[(J) + 96]);

// Selection for one batch: warp-coherent prefilter, prefix-scan push, drain.
#define PROCESS(JB)                                                           \
    {                                                                         \
        float mn = fminf(fminf(fminf(d0, d1), fminf(d2, d3)),                 \
                         fminf(fminf(d4, d5), fminf(d6, d7)));                \
        if (__any_sync(FULLM, mn <= thr)) {                                   \
            int c0 = d0 <= thr, c1 = d1 <= thr, c2 = d2 <= thr, c3 = d3 <= thr; \
            int c4 = d4 <= thr, c5 = d5 <= thr, c6 = d6 <= thr, c7 = d7 <= thr; \
            int cnt = c0 + c1 + c2 + c3 + c4 + c5 + c6 + c7;                  \
            int scan = cnt;                                                   \
            _Pragma("unroll")                                                 \
            for (int s = 1; s < 32; s <<= 1) {                                \
                int y = __shfl_up_sync(FULLM, scan, s);                       \
                if (lane >= s) scan += y;                                     \
            }                                                                 \
            int total = __shfl_sync(FULLM, scan, 31);                         \
            if (total) {                                                      \
                int off = count + scan - cnt;                                 \
                if (c0) buf[off++] = MKKEY(d0, 2 * (JB));                     \
                if (c1) buf[off++] = MKKEY(d1, 2 * (JB) + 1);                 \
                if (c2) buf[off++] = MKKEY(d2, 2 * ((JB) + 32));              \
                if (c3) buf[off++] = MKKEY(d3, 2 * ((JB) + 32) + 1);          \
                if (c4) buf[off++] = MKKEY(d4, 2 * ((JB) + 64));              \
                if (c5) buf[off++] = MKKEY(d5, 2 * ((JB) + 64) + 1);          \
                if (c6) buf[off++] = MKKEY(d6, 2 * ((JB) + 96));              \
                if (c7) buf[off++] = MKKEY(d7, 2 * ((JB) + 96) + 1);          \
                count += total;                                               \
                if (count >= TRIG) drain(top, buf, count, lane, thr);         \
            }                                                                 \
        }                                                                     \
    }

__global__ __launch_bounds__(32 * WPB, 5)
void knn_idw_kernel(const float* __restrict__ x,    // [NB, NS, NC]
                    const float* __restrict__ rel,  // [NT, NS, 2]
                    float* __restrict__ out)        // [NB, NT, NC]
{
    __shared__ ull sbuf[WPB][BUFCAP];

    const int warp = threadIdx.x >> 5;
    const int lane = threadIdx.x & 31;
    const int t    = blockIdx.x * WPB + warp;     // target index (grid covers NT)
    ull* buf = sbuf[warp];

    const float4* relrow = reinterpret_cast<const float4*>(rel + (size_t)t * NS * 2);

    // Distributed warp top-10: lane k (k<10) holds k-th smallest key.
    // key = (float_bits(d2) << 32) | source_index  -> exact order, ties by lowest idx.
    ull   top   = ~0ULL;
    float thr;
    int   count = 0;

    // ---- Prefetch distance 1 (4 LDG.128 in flight; MLP comes from 40 warps/SM) ----
    float4 v0, v1, v2, v3;
    LOAD4(v0, v1, v2, v3, lane);                  // batch 0

    // ---- Batch 0 (peeled): seed thr from lane-mins, then push its survivors ----
    {
        const int jb = lane;
        DIST8(v0, v1, v2, v3);
        LOAD4(v0, v1, v2, v3, lane + 128);        // prefetch batch 1
        float mn = fminf(fminf(fminf(d0, d1), fminf(d2, d3)),
                         fminf(fminf(d4, d5), fminf(d6, d7)));
        // thr = 10th-smallest of 32 lane-mins. The 10 smallest lane-mins are 10
        // distinct elements, so thr >= global 10th-smallest of batch 0 (and of
        // anything seen so far) -> no true top-10 member is ever rejected.
        ull sorted = bitonic32(MKKEY(mn, lane), lane);
        thr = __uint_as_float((unsigned)(__shfl_sync(FULLM, sorted, NH - 1) >> 32));
        PROCESS(jb);
    }

    // ---- Steady state: batches 1..15 ----
#pragma unroll 1
    for (int b = 1; b < 16; ++b) {
        const int jb = b * 128 + lane;
        DIST8(v0, v1, v2, v3);
        if (b < 15) { LOAD4(v0, v1, v2, v3, jb + 128); }   // prefetch next batch
        PROCESS(jb);
    }

    if (count > 0) drain(top, buf, count, lane, thr);

    // ---- Weights ----
    float wk[NH];
    int   ik[NH];
    float wsum = 0.0f;
#pragma unroll
    for (int k = 0; k < NH; ++k) {
        ull kk = __shfl_sync(FULLM, top, k);
        float dd = __uint_as_float((unsigned)(kk >> 32));
        ik[k] = (int)(kk & 0xFFFFFFFFu);
        float w = 1.0f / (sqrtf(dd) + 1e-10f);
        wk[k] = w;
        wsum += w;
    }
    const float inv = 1.0f / wsum;

    // ---- Gather + weighted sum: 64 outputs (8 batch x 8 chan), 2 per lane ----
    const int bb = lane >> 3;      // 0..3
    const int c  = lane & 7;       // 0..7
    float acc0 = 0.0f, acc1 = 0.0f;
#pragma unroll
    for (int k = 0; k < NH; ++k) {
        float w = wk[k] * inv;
        const float* xs = x + (size_t)ik[k] * NC + c;
        acc0 += w * __ldg(xs + (size_t)(bb)     * NS * NC);
        acc1 += w * __ldg(xs + (size_t)(bb + 4) * NS * NC);
    }
    out[((size_t)(bb)     * NT + t) * NC + c] = acc0;
    out[((size_t)(bb + 4) * NT + t) * NC + c] = acc1;
}

extern "C" void kernel_launch(void* const* d_in, const int* in_sizes, int n_in,
                              void* d_out, int out_size)
{
    const float* x   = (const float*)d_in[0];   // [8, 4096, 8]
    const float* rel = (const float*)d_in[1];   // [16384, 4096, 2]
    float* out       = (float*)d_out;           // [8, 16384, 8]
    (void)in_sizes; (void)n_in; (void)out_size;

    dim3 grid(NT / WPB);      // 2048 blocks
    dim3 block(32 * WPB);     // 256 threads
    knn_idw_kernel<<<grid, block>>>(x, rel, out);
}